// round 1
// baseline (speedup 1.0000x reference)
#include <cuda_runtime.h>
#include <math.h>

// ---------------- dimensions ----------------
// b=8, m=1024, d=768, n=64, p=16, h=1536, s=n*p=1024
#define DB 8
#define DM 1024
#define DD 768
#define DN 64
#define DP 16
#define DH 1536
#define DS 1024   // n*p

// ---------------- scratch (device globals; no allocs allowed) ----------------
__device__ float g_phin[DN * DP * DD];          // 786432
__device__ float g_logits[DB * DM * DS];        // 8388608
__device__ float g_D[DB * DM * DS];             // dispatch softmax (over m), layout [b][m][s]
__device__ float g_C[DB * DM * DS];             // combine softmax (over s), layout [b][m][s]
__device__ float g_Xs[DB * DS * DD];            // 6291456  [b][n][p][d]
__device__ float g_hdn[DN * (DB * DP) * DH];    // 12582912 [n][128][h]
__device__ float g_Ys[DB * DS * DD];            // 6291456  [b][s][d]

// ---------------- phi normalize over expert axis ----------------
__global__ void phi_norm_kernel(const float* __restrict__ phi, float* __restrict__ phin) {
    int i = blockIdx.x * blockDim.x + threadIdx.x;  // 0 .. 16*768-1
    if (i >= DP * DD) return;
    float s = 0.f;
#pragma unroll 4
    for (int n = 0; n < DN; n++) {
        float v = phi[n * (DP * DD) + i];
        s += v * v;
    }
    float r = rsqrtf(s + 1e-6f);
#pragma unroll 4
    for (int n = 0; n < DN; n++) {
        phin[n * (DP * DD) + i] = phi[n * (DP * DD) + i] * r;
    }
}

// ---------------- row softmax (over s=1024), one block per (b,m) row ----------------
__global__ void softmax_row_kernel(const float* __restrict__ L, float* __restrict__ O) {
    const float* Lr = L + (size_t)blockIdx.x * DS;
    float* Or = O + (size_t)blockIdx.x * DS;
    int t = threadIdx.x;
    float v[4];
    float mx = -1e30f;
#pragma unroll
    for (int j = 0; j < 4; j++) {
        v[j] = Lr[t + j * 256];
        mx = fmaxf(mx, v[j]);
    }
    __shared__ float sd[256];
    sd[t] = mx;
    __syncthreads();
    for (int off = 128; off > 0; off >>= 1) {
        if (t < off) sd[t] = fmaxf(sd[t], sd[t + off]);
        __syncthreads();
    }
    mx = sd[0];
    __syncthreads();
    float sum = 0.f;
#pragma unroll
    for (int j = 0; j < 4; j++) {
        v[j] = expf(v[j] - mx);
        sum += v[j];
    }
    sd[t] = sum;
    __syncthreads();
    for (int off = 128; off > 0; off >>= 1) {
        if (t < off) sd[t] += sd[t + off];
        __syncthreads();
    }
    float inv = 1.f / sd[0];
#pragma unroll
    for (int j = 0; j < 4; j++) Or[t + j * 256] = v[j] * inv;
}

// ---------------- column softmax over m (dispatch), coalesced across s ----------------
// grid: (DS/32, DB), block: (32, 8)
__global__ void softmax_col_kernel(const float* __restrict__ L, float* __restrict__ O) {
    int b = blockIdx.y;
    int s = blockIdx.x * 32 + threadIdx.x;
    int ty = threadIdx.y;  // 0..7
    const float* Lb = L + (size_t)b * DM * DS;
    float* Ob = O + (size_t)b * DM * DS;
    __shared__ float red[8][32];
    float mx = -1e30f;
    for (int m = ty; m < DM; m += 8) mx = fmaxf(mx, Lb[(size_t)m * DS + s]);
    red[ty][threadIdx.x] = mx;
    __syncthreads();
    if (ty == 0) {
        float v = red[0][threadIdx.x];
#pragma unroll
        for (int i = 1; i < 8; i++) v = fmaxf(v, red[i][threadIdx.x]);
        red[0][threadIdx.x] = v;
    }
    __syncthreads();
    mx = red[0][threadIdx.x];
    __syncthreads();
    float sum = 0.f;
    for (int m = ty; m < DM; m += 8) sum += expf(Lb[(size_t)m * DS + s] - mx);
    red[ty][threadIdx.x] = sum;
    __syncthreads();
    if (ty == 0) {
        float v = 0.f;
#pragma unroll
        for (int i = 0; i < 8; i++) v += red[i][threadIdx.x];
        red[0][threadIdx.x] = v;
    }
    __syncthreads();
    float inv = 1.f / red[0][threadIdx.x];
    for (int m = ty; m < DM; m += 8) {
        Ob[(size_t)m * DS + s] = expf(Lb[(size_t)m * DS + s] - mx) * inv;
    }
}

// ---------------- LayerNorm in place, one block per (b,n,p) row of 768 ----------------
__global__ void layernorm_kernel(float* __restrict__ X, const float* __restrict__ g,
                                 const float* __restrict__ bb) {
    int row = blockIdx.x;              // b*1024 + n*16 + p
    int n = (row & 1023) >> 4;
    float* Xr = X + (size_t)row * DD;
    __shared__ float sh[DD];
    __shared__ float red[256];
    int t = threadIdx.x;
    float ls = 0.f;
    for (int j = t; j < DD; j += 256) {
        float v = Xr[j];
        sh[j] = v;
        ls += v;
    }
    red[t] = ls;
    __syncthreads();
    for (int off = 128; off > 0; off >>= 1) {
        if (t < off) red[t] += red[t + off];
        __syncthreads();
    }
    float mu = red[0] * (1.0f / DD);
    __syncthreads();
    float lv = 0.f;
    for (int j = t; j < DD; j += 256) {
        float dv = sh[j] - mu;
        lv += dv * dv;
    }
    red[t] = lv;
    __syncthreads();
    for (int off = 128; off > 0; off >>= 1) {
        if (t < off) red[t] += red[t + off];
        __syncthreads();
    }
    float is = rsqrtf(red[0] * (1.0f / DD) + 1e-5f);
    __syncthreads();
    for (int j = t; j < DD; j += 256) {
        Xr[j] = (sh[j] - mu) * is * g[n * DD + j] + bb[n * DD + j];
    }
}

// ---------------- templated tiled SGEMM 128x128x8, 8x8 microtile ----------------
// AMODE: 0 = row-major [M][K], 1 = transposed [K][M], 2 = gathered rows (expert)
// BMODE: 0 = row-major [K][N], 1 = row-major [N][K] (computes A @ B^T)
// EPI:   0 = none, 1 = +bias[col], 2 = +bias[col] then exact GELU
// CSC:   0 = row-major [M][ldc], 1 = scattered rows (expert output)
#define BMT 128
#define BNT 128
#define BKT 8

template <int AMODE, int BMODE, int EPI, int CSC>
__global__ __launch_bounds__(256)
void gemm_kernel(const float* __restrict__ A, const float* __restrict__ B,
                 float* __restrict__ C, const float* __restrict__ bias,
                 int M, int N, int K, int lda, int ldb, int ldc,
                 long long aBS, long long bBS, long long cBS, long long biasBS,
                 long long a_sb, long long a_sp, long long c_sb, long long c_sp) {
    __shared__ float As[BKT][BMT];
    __shared__ float Bs[BKT][BNT];
    int z = blockIdx.z;
    A += z * aBS;
    B += z * bBS;
    C += z * cBS;
    if (EPI >= 1) bias += z * biasBS;
    int bm = blockIdx.y * BMT;
    int bn = blockIdx.x * BNT;
    int tid = threadIdx.x;
    int tx = tid & 15, ty = tid >> 4;

    float acc[8][8];
#pragma unroll
    for (int i = 0; i < 8; i++)
#pragma unroll
        for (int j = 0; j < 8; j++) acc[i][j] = 0.f;

    for (int k0 = 0; k0 < K; k0 += BKT) {
        // ---- load A tile ----
        if (AMODE == 0) {
            int ar = tid >> 1;
            int ac = (tid & 1) * 4;
            float4 v = *(const float4*)(A + (size_t)(bm + ar) * lda + k0 + ac);
            As[ac + 0][ar] = v.x;
            As[ac + 1][ar] = v.y;
            As[ac + 2][ar] = v.z;
            As[ac + 3][ar] = v.w;
        } else if (AMODE == 1) {
            int kk = tid >> 5;
            int mc = (tid & 31) * 4;
            float4 v = *(const float4*)(A + (size_t)(k0 + kk) * lda + bm + mc);
            *(float4*)&As[kk][mc] = v;
        } else {
            int ar = tid >> 1;
            int ac = (tid & 1) * 4;
            const float* rowp = A + (size_t)(ar >> 4) * a_sb + (size_t)(ar & 15) * a_sp;
            float4 v = *(const float4*)(rowp + k0 + ac);
            As[ac + 0][ar] = v.x;
            As[ac + 1][ar] = v.y;
            As[ac + 2][ar] = v.z;
            As[ac + 3][ar] = v.w;
        }
        // ---- load B tile ----
        if (BMODE == 0) {
            int kk = tid >> 5;
            int nc = (tid & 31) * 4;
            float4 v = *(const float4*)(B + (size_t)(k0 + kk) * ldb + bn + nc);
            *(float4*)&Bs[kk][nc] = v;
        } else {
            int br = tid >> 1;
            int bc = (tid & 1) * 4;
            float4 v = *(const float4*)(B + (size_t)(bn + br) * ldb + k0 + bc);
            Bs[bc + 0][br] = v.x;
            Bs[bc + 1][br] = v.y;
            Bs[bc + 2][br] = v.z;
            Bs[bc + 3][br] = v.w;
        }
        __syncthreads();
#pragma unroll
        for (int k = 0; k < BKT; k++) {
            float4 a0 = *(const float4*)&As[k][ty * 8];
            float4 a1 = *(const float4*)&As[k][ty * 8 + 4];
            float4 b0 = *(const float4*)&Bs[k][tx * 8];
            float4 b1 = *(const float4*)&Bs[k][tx * 8 + 4];
            float ra[8] = {a0.x, a0.y, a0.z, a0.w, a1.x, a1.y, a1.z, a1.w};
            float rb[8] = {b0.x, b0.y, b0.z, b0.w, b1.x, b1.y, b1.z, b1.w};
#pragma unroll
            for (int i = 0; i < 8; i++)
#pragma unroll
                for (int j = 0; j < 8; j++) acc[i][j] += ra[i] * rb[j];
        }
        __syncthreads();
    }

    // ---- epilogue ----
#pragma unroll
    for (int i = 0; i < 8; i++) {
        int row = bm + ty * 8 + i;
        float* crow;
        if (CSC == 1)
            crow = C + (size_t)(row >> 4) * c_sb + (size_t)(row & 15) * c_sp;
        else
            crow = C + (size_t)row * ldc;
#pragma unroll
        for (int j = 0; j < 8; j++) {
            int col = bn + tx * 8 + j;
            float v = acc[i][j];
            if (EPI >= 1) v += bias[col];
            if (EPI == 2) v = 0.5f * v * (1.0f + erff(v * 0.70710678118654752440f));
            crow[col] = v;
        }
    }
}

// ---------------- host launcher ----------------
extern "C" void kernel_launch(void* const* d_in, const int* in_sizes, int n_in,
                              void* d_out, int out_size) {
    const float* x    = (const float*)d_in[0];
    const float* phi  = (const float*)d_in[1];
    const float* ln_g = (const float*)d_in[2];
    const float* ln_b = (const float*)d_in[3];
    const float* w1   = (const float*)d_in[4];
    const float* b1   = (const float*)d_in[5];
    const float* w2   = (const float*)d_in[6];
    const float* b2   = (const float*)d_in[7];
    float* out = (float*)d_out;

    float *phin, *logits, *Dbuf, *Cbuf, *Xs, *hdn, *Ys;
    cudaGetSymbolAddress((void**)&phin, g_phin);
    cudaGetSymbolAddress((void**)&logits, g_logits);
    cudaGetSymbolAddress((void**)&Dbuf, g_D);
    cudaGetSymbolAddress((void**)&Cbuf, g_C);
    cudaGetSymbolAddress((void**)&Xs, g_Xs);
    cudaGetSymbolAddress((void**)&hdn, g_hdn);
    cudaGetSymbolAddress((void**)&Ys, g_Ys);

    // 1. normalize phi over expert axis
    phi_norm_kernel<<<(DP * DD + 255) / 256, 256>>>(phi, phin);

    // 2. logits[8192,1024] = x[8192,768] @ phin[1024,768]^T   (NT)
    gemm_kernel<0, 1, 0, 0><<<dim3(DS / BNT, (DB * DM) / BMT, 1), 256>>>(
        x, phin, logits, nullptr, DB * DM, DS, DD, DD, DD, DS,
        0, 0, 0, 0, 0, 0, 0, 0);

    // 3a. combine softmax over s  -> C [b][m][s]
    softmax_row_kernel<<<DB * DM, 256>>>(logits, Cbuf);
    // 3b. dispatch softmax over m -> D [b][m][s]
    softmax_col_kernel<<<dim3(DS / 32, DB), dim3(32, 8)>>>(logits, Dbuf);

    // 4. Xs[b][s][d] = D_b^T @ x_b   (TN, batched over b)
    gemm_kernel<1, 0, 0, 0><<<dim3(DD / BNT, DS / BMT, DB), 256>>>(
        Dbuf, x, Xs, nullptr, DS, DD, DM, DS, DD, DD,
        (long long)DM * DS, (long long)DM * DD, (long long)DS * DD, 0, 0, 0, 0, 0);

    // 5. LayerNorm in place
    layernorm_kernel<<<DB * DS, 256>>>(Xs, ln_g, ln_b);

    // 6. expert GEMM1: hdn[n][128][h] = gather(Xs) @ w1[n] + b1[n], GELU
    gemm_kernel<2, 0, 2, 0><<<dim3(DH / BNT, 1, DN), 256>>>(
        Xs, w1, hdn, b1, DB * DP, DH, DD, DD, DH, DH,
        (long long)DP * DD,            // A batch: + n*16*768
        (long long)DD * DH,            // B batch: w1 expert stride
        (long long)(DB * DP) * DH,     // C batch: hdn expert stride
        DH,                            // bias stride
        (long long)DS * DD,            // a_sb: batch b stride in Xs
        DD,                            // a_sp: p stride
        0, 0);

    // 7. expert GEMM2: Ys[b][n*16+p][d] = hdn[n] @ w2[n] + b2[n]  (scattered C)
    gemm_kernel<0, 0, 1, 1><<<dim3(DD / BNT, 1, DN), 256>>>(
        hdn, w2, Ys, b2, DB * DP, DD, DH, DH, DD, DD,
        (long long)(DB * DP) * DH,     // A batch: hdn expert stride
        (long long)DH * DD,            // B batch: w2 expert stride
        (long long)DP * DD,            // C batch: + n*16*768
        DD,                            // bias stride
        0, 0,
        (long long)DS * DD,            // c_sb: batch b stride in Ys
        DD);                           // c_sp: p stride

    // 8. Y[b][m][d] = C_b @ Ys_b   (NN, batched over b)
    gemm_kernel<0, 0, 0, 0><<<dim3(DD / BNT, DM / BMT, DB), 256>>>(
        Cbuf, Ys, out, nullptr, DM, DD, DS, DS, DD, DD,
        (long long)DM * DS, (long long)DS * DD, (long long)DM * DD, 0, 0, 0, 0, 0);
}

// round 3
// speedup vs baseline: 2.1923x; 2.1923x over previous
#include <cuda_runtime.h>
#include <cuda_bf16.h>
#include <math.h>
#include <cstdint>

// ---------------- dimensions ----------------
#define DB 8
#define DM 1024
#define DD 768
#define DN 64
#define DP 16
#define DH 1536
#define DS 1024   // n*p

// ---------------- scratch ----------------
__device__ float g_phin[DN * DP * DD];
__device__ float g_logits[DB * DM * DS];
__device__ float g_D[DB * DM * DS];
__device__ float g_C[DB * DM * DS];
__device__ float g_Xs[DB * DS * DD];
__device__ float g_LN[DN * DB * DP * DD];       // [n][b*16+p][d]
__device__ float g_hdn[DN * (DB * DP) * DH];    // [n][128][h]
__device__ float g_Ys[DB * DS * DD];            // [b][s][d]

// ================= helpers =================
__device__ __forceinline__ uint32_t smem_to_u32(const void* p) {
    uint32_t a;
    asm("{ .reg .u64 t; cvta.to.shared.u64 t, %1; cvt.u32.u64 %0, t; }" : "=r"(a) : "l"(p));
    return a;
}

__device__ __forceinline__ void split2(float x, float y, uint32_t& h, uint32_t& lo) {
    __nv_bfloat162 hv, lv;
    hv.x = __float2bfloat16(x);
    hv.y = __float2bfloat16(y);
    lv.x = __float2bfloat16(x - __bfloat162float(hv.x));
    lv.y = __float2bfloat16(y - __bfloat162float(hv.y));
    h = *(uint32_t*)&hv;
    lo = *(uint32_t*)&lv;
}

__device__ __forceinline__ void ldsm_x4(uint32_t* r, uint32_t addr) {
    asm volatile("ldmatrix.sync.aligned.m8n8.x4.shared.b16 {%0,%1,%2,%3}, [%4];"
                 : "=r"(r[0]), "=r"(r[1]), "=r"(r[2]), "=r"(r[3]) : "r"(addr));
}
__device__ __forceinline__ void ldsm_x4_t(uint32_t* r, uint32_t addr) {
    asm volatile("ldmatrix.sync.aligned.m8n8.x4.trans.shared.b16 {%0,%1,%2,%3}, [%4];"
                 : "=r"(r[0]), "=r"(r[1]), "=r"(r[2]), "=r"(r[3]) : "r"(addr));
}
__device__ __forceinline__ void ldsm_x2(uint32_t* r, uint32_t addr) {
    asm volatile("ldmatrix.sync.aligned.m8n8.x2.shared.b16 {%0,%1}, [%2];"
                 : "=r"(r[0]), "=r"(r[1]) : "r"(addr));
}
__device__ __forceinline__ void ldsm_x2_t(uint32_t* r, uint32_t addr) {
    asm volatile("ldmatrix.sync.aligned.m8n8.x2.trans.shared.b16 {%0,%1}, [%2];"
                 : "=r"(r[0]), "=r"(r[1]) : "r"(addr));
}
__device__ __forceinline__ void mma_bf16(float* d, const uint32_t* a, const uint32_t* b) {
    asm volatile(
        "mma.sync.aligned.m16n8k16.row.col.f32.bf16.bf16.f32 "
        "{%0,%1,%2,%3}, {%4,%5,%6,%7}, {%8,%9}, {%0,%1,%2,%3};"
        : "+f"(d[0]), "+f"(d[1]), "+f"(d[2]), "+f"(d[3])
        : "r"(a[0]), "r"(a[1]), "r"(a[2]), "r"(a[3]), "r"(b[0]), "r"(b[1]));
}

// ================= elementwise kernels =================
__global__ void phi_norm_kernel(const float* __restrict__ phi, float* __restrict__ phin) {
    int i = blockIdx.x * blockDim.x + threadIdx.x;
    if (i >= DP * DD) return;
    float s = 0.f;
#pragma unroll 4
    for (int n = 0; n < DN; n++) { float v = phi[n * (DP * DD) + i]; s += v * v; }
    float r = rsqrtf(s + 1e-6f);
#pragma unroll 4
    for (int n = 0; n < DN; n++) phin[n * (DP * DD) + i] = phi[n * (DP * DD) + i] * r;
}

__global__ void softmax_row_kernel(const float* __restrict__ L, float* __restrict__ O) {
    const float* Lr = L + (size_t)blockIdx.x * DS;
    float* Or = O + (size_t)blockIdx.x * DS;
    int t = threadIdx.x;
    float v[4]; float mx = -1e30f;
#pragma unroll
    for (int j = 0; j < 4; j++) { v[j] = Lr[t + j * 256]; mx = fmaxf(mx, v[j]); }
    __shared__ float sd[256];
    sd[t] = mx; __syncthreads();
    for (int off = 128; off > 0; off >>= 1) { if (t < off) sd[t] = fmaxf(sd[t], sd[t + off]); __syncthreads(); }
    mx = sd[0]; __syncthreads();
    float sum = 0.f;
#pragma unroll
    for (int j = 0; j < 4; j++) { v[j] = expf(v[j] - mx); sum += v[j]; }
    sd[t] = sum; __syncthreads();
    for (int off = 128; off > 0; off >>= 1) { if (t < off) sd[t] += sd[t + off]; __syncthreads(); }
    float inv = 1.f / sd[0];
#pragma unroll
    for (int j = 0; j < 4; j++) Or[t + j * 256] = v[j] * inv;
}

__global__ void softmax_col_kernel(const float* __restrict__ L, float* __restrict__ O) {
    int b = blockIdx.y;
    int s = blockIdx.x * 32 + threadIdx.x;
    int ty = threadIdx.y;
    const float* Lb = L + (size_t)b * DM * DS;
    float* Ob = O + (size_t)b * DM * DS;
    __shared__ float red[8][32];
    float mx = -1e30f;
    for (int m = ty; m < DM; m += 8) mx = fmaxf(mx, Lb[(size_t)m * DS + s]);
    red[ty][threadIdx.x] = mx; __syncthreads();
    if (ty == 0) {
        float v = red[0][threadIdx.x];
#pragma unroll
        for (int i = 1; i < 8; i++) v = fmaxf(v, red[i][threadIdx.x]);
        red[0][threadIdx.x] = v;
    }
    __syncthreads();
    mx = red[0][threadIdx.x]; __syncthreads();
    float sum = 0.f;
    for (int m = ty; m < DM; m += 8) sum += expf(Lb[(size_t)m * DS + s] - mx);
    red[ty][threadIdx.x] = sum; __syncthreads();
    if (ty == 0) {
        float v = 0.f;
#pragma unroll
        for (int i = 0; i < 8; i++) v += red[i][threadIdx.x];
        red[0][threadIdx.x] = v;
    }
    __syncthreads();
    float inv = 1.f / red[0][threadIdx.x];
    for (int m = ty; m < DM; m += 8)
        Ob[(size_t)m * DS + s] = expf(Lb[(size_t)m * DS + s] - mx) * inv;
}

// LayerNorm: read Xs [b][n*16+p][d], write LN [n][b*16+p][d]
__global__ void layernorm_kernel(const float* __restrict__ X, float* __restrict__ Yo,
                                 const float* __restrict__ g, const float* __restrict__ bb) {
    int row = blockIdx.x;
    int b = row >> 10;
    int slot = row & 1023;
    int n = slot >> 4;
    int p = slot & 15;
    const float* Xr = X + (size_t)row * DD;
    float* Yr = Yo + ((size_t)n * 128 + b * 16 + p) * DD;
    __shared__ float sh[DD];
    __shared__ float red[256];
    int t = threadIdx.x;
    float ls = 0.f;
    for (int j = t; j < DD; j += 256) { float v = Xr[j]; sh[j] = v; ls += v; }
    red[t] = ls; __syncthreads();
    for (int off = 128; off > 0; off >>= 1) { if (t < off) red[t] += red[t + off]; __syncthreads(); }
    float mu = red[0] * (1.0f / DD); __syncthreads();
    float lv = 0.f;
    for (int j = t; j < DD; j += 256) { float dv = sh[j] - mu; lv += dv * dv; }
    red[t] = lv; __syncthreads();
    for (int off = 128; off > 0; off >>= 1) { if (t < off) red[t] += red[t + off]; __syncthreads(); }
    float is = rsqrtf(red[0] * (1.0f / DD) + 1e-5f); __syncthreads();
    for (int j = t; j < DD; j += 256)
        Yr[j] = (sh[j] - mu) * is * g[n * DD + j] + bb[n * DD + j];
}

// ================= mma.sync GEMM =================
// CTA tile 128x128, kc=32, 3-term bf16 split, double-buffered smem.
// TA/TB: 0 = row-major [row][K], 1 = K-major [K][row]
// EPI: 0 none, 1 +bias, 2 +bias+gelu ; CSC: 1 = scattered output rows
template <int TA, int TB, int EPI, int CSC>
__global__ void __launch_bounds__(256)
gemm_mma(const float* __restrict__ A, const float* __restrict__ B,
         float* __restrict__ C, const float* __restrict__ bias,
         int K, int lda, int ldb, int ldc,
         long long aBS, long long bBS, long long cBS, int biasBS, long long c_sb) {
    constexpr int AROW = TA ? 272 : 80;        // bytes per smem row (one of hi/lo)
    constexpr int ASZ1 = TA ? 32 * 272 : 128 * 80;
    constexpr int BROW = TB ? 272 : 80;
    constexpr int BSZ1 = TB ? 32 * 272 : 128 * 80;
    constexpr int STAGE = 2 * ASZ1 + 2 * BSZ1;
    extern __shared__ char smem[];
    const uint32_t sm0 = smem_to_u32(smem);

    const int tid = threadIdx.x;
    const int l = tid & 31;
    const int wid = tid >> 5;
    const int wm = wid & 3;         // 4 M groups of 32 rows
    const int wn = wid >> 2;        // 2 N groups of 64 cols
    const int z = blockIdx.z;
    const int bm = blockIdx.y * 128;
    const int bn = blockIdx.x * 128;
    const int NC = K >> 5;

    const float* Ab = A + (size_t)z * aBS + (TA ? (size_t)bm : (size_t)bm * lda);
    const float* Bb = B + (size_t)z * bBS + (TB ? (size_t)bn : (size_t)bn * ldb);

    int a_r, a_c, b_r, b_c;
    if (TA) { a_r = tid >> 3; a_c = (tid & 7) * 16; } else { a_r = tid >> 1; a_c = (tid & 1) * 16; }
    if (TB) { b_r = tid >> 3; b_c = (tid & 7) * 16; } else { b_r = tid >> 1; b_c = (tid & 1) * 16; }

    float4 ra[4], rb[4];

    auto LDG = [&](int c) {
        int k0 = c * 32;
        const float* ap = TA ? (Ab + (size_t)(k0 + a_r) * lda + a_c)
                             : (Ab + (size_t)a_r * lda + k0 + a_c);
        const float* bp = TB ? (Bb + (size_t)(k0 + b_r) * ldb + b_c)
                             : (Bb + (size_t)b_r * ldb + k0 + b_c);
#pragma unroll
        for (int i = 0; i < 4; i++) {
            ra[i] = *(const float4*)(ap + 4 * i);
            rb[i] = *(const float4*)(bp + 4 * i);
        }
    };

    auto STS = [&](int s) {
        char* st = smem + s * STAGE;
        char* ahis = st;
        char* alos = st + ASZ1;
        char* bhis = st + 2 * ASZ1;
        char* blos = st + 2 * ASZ1 + BSZ1;
        int aoff = a_r * AROW + a_c * 2;
        int boff = b_r * BROW + b_c * 2;
#pragma unroll
        for (int i = 0; i < 4; i++) {
            uint32_t h0, l0, h1, l1;
            split2(ra[i].x, ra[i].y, h0, l0);
            split2(ra[i].z, ra[i].w, h1, l1);
            *(uint2*)(ahis + aoff + i * 8) = make_uint2(h0, h1);
            *(uint2*)(alos + aoff + i * 8) = make_uint2(l0, l1);
            split2(rb[i].x, rb[i].y, h0, l0);
            split2(rb[i].z, rb[i].w, h1, l1);
            *(uint2*)(bhis + boff + i * 8) = make_uint2(h0, h1);
            *(uint2*)(blos + boff + i * 8) = make_uint2(l0, l1);
        }
    };

    float acc[2][8][4];
#pragma unroll
    for (int mt = 0; mt < 2; mt++)
#pragma unroll
        for (int nt = 0; nt < 8; nt++)
#pragma unroll
            for (int q = 0; q < 4; q++) acc[mt][nt][q] = 0.f;

    auto COMPUTE = [&](int s) {
        uint32_t sbA = sm0 + s * STAGE;
        uint32_t sbB = sbA + 2 * ASZ1;
#pragma unroll
        for (int ks = 0; ks < 2; ks++) {
            uint32_t ahi[2][4], alo[2][4];
#pragma unroll
            for (int mt = 0; mt < 2; mt++) {
                int mr = wm * 32 + mt * 16;
                if (TA) {
                    int krow = ks * 16 + (l & 7) + ((l >> 4) << 3);
                    int col = mr + (((l >> 3) & 1) << 3);
                    uint32_t addr = sbA + krow * 272 + col * 2;
                    ldsm_x4_t(ahi[mt], addr);
                    ldsm_x4_t(alo[mt], addr + ASZ1);
                } else {
                    int row = mr + (l & 15);
                    uint32_t addr = sbA + row * 80 + ks * 32 + ((l >> 4) & 1) * 16;
                    ldsm_x4(ahi[mt], addr);
                    ldsm_x4(alo[mt], addr + ASZ1);
                }
            }
#pragma unroll
            for (int nt = 0; nt < 8; nt++) {
                int nr = wn * 64 + nt * 8;
                uint32_t bhi[2], blo[2];
                if (TB) {
                    int krow = ks * 16 + (l & 7) + (((l >> 3) & 1) << 3);
                    uint32_t addr = sbB + krow * 272 + nr * 2;
                    ldsm_x2_t(bhi, addr);
                    ldsm_x2_t(blo, addr + BSZ1);
                } else {
                    uint32_t addr = sbB + (nr + (l & 7)) * 80 + ks * 32 + (((l >> 3) & 1) << 4);
                    ldsm_x2(bhi, addr);
                    ldsm_x2(blo, addr + BSZ1);
                }
#pragma unroll
                for (int mt = 0; mt < 2; mt++) {
                    mma_bf16(acc[mt][nt], ahi[mt], bhi);
                    mma_bf16(acc[mt][nt], alo[mt], bhi);
                    mma_bf16(acc[mt][nt], ahi[mt], blo);
                }
            }
        }
    };

    LDG(0);
    STS(0);
    __syncthreads();
    for (int c = 0; c < NC; c++) {
        if (c + 1 < NC) LDG(c + 1);
        COMPUTE(c & 1);
        __syncthreads();
        if (c + 1 < NC) {
            STS((c + 1) & 1);
            __syncthreads();
        }
    }

    // ---------------- epilogue via smem staging ----------------
    float* Cs = (float*)smem;   // [128][132]
#pragma unroll
    for (int mt = 0; mt < 2; mt++) {
#pragma unroll
        for (int nt = 0; nt < 8; nt++) {
            int r0 = wm * 32 + mt * 16 + (l >> 2);
            int c0 = wn * 64 + nt * 8 + (l & 3) * 2;
            Cs[r0 * 132 + c0] = acc[mt][nt][0];
            Cs[r0 * 132 + c0 + 1] = acc[mt][nt][1];
            Cs[(r0 + 8) * 132 + c0] = acc[mt][nt][2];
            Cs[(r0 + 8) * 132 + c0 + 1] = acc[mt][nt][3];
        }
    }
    __syncthreads();
    const float* bp = (EPI >= 1) ? (bias + (size_t)z * biasBS + bn) : nullptr;
#pragma unroll 4
    for (int i = 0; i < 64; i++) {
        int idx = i * 256 + tid;
        int r = idx >> 7, cc = idx & 127;
        float v = Cs[r * 132 + cc];
        if (EPI >= 1) v += __ldg(bp + cc);
        if (EPI == 2) v = 0.5f * v * (1.0f + erff(v * 0.70710678118654752440f));
        size_t off;
        if (CSC)
            off = (size_t)z * cBS + (size_t)(r >> 4) * c_sb + (size_t)(r & 15) * ldc + bn + cc;
        else
            off = (size_t)z * cBS + (size_t)(bm + r) * ldc + bn + cc;
        C[off] = v;
    }
}

// ================= host launcher =================
extern "C" void kernel_launch(void* const* d_in, const int* in_sizes, int n_in,
                              void* d_out, int out_size) {
    const float* x    = (const float*)d_in[0];
    const float* phi  = (const float*)d_in[1];
    const float* ln_g = (const float*)d_in[2];
    const float* ln_b = (const float*)d_in[3];
    const float* w1   = (const float*)d_in[4];
    const float* b1   = (const float*)d_in[5];
    const float* w2   = (const float*)d_in[6];
    const float* b2   = (const float*)d_in[7];
    float* out = (float*)d_out;

    float *phin, *logits, *Dbuf, *Cbuf, *Xs, *LN, *hdn, *Ys;
    cudaGetSymbolAddress((void**)&phin, g_phin);
    cudaGetSymbolAddress((void**)&logits, g_logits);
    cudaGetSymbolAddress((void**)&Dbuf, g_D);
    cudaGetSymbolAddress((void**)&Cbuf, g_C);
    cudaGetSymbolAddress((void**)&Xs, g_Xs);
    cudaGetSymbolAddress((void**)&LN, g_LN);
    cudaGetSymbolAddress((void**)&hdn, g_hdn);
    cudaGetSymbolAddress((void**)&Ys, g_Ys);

    // smem sizes: 2*STAGE per variant
    const int SM00 = 2 * (2 * 128 * 80 + 2 * 128 * 80);       // 81920
    const int SM11 = 2 * (2 * 32 * 272 + 2 * 32 * 272);       // 69632
    const int SM01 = 2 * (2 * 128 * 80 + 2 * 32 * 272);       // 75776
    cudaFuncSetAttribute(gemm_mma<0,0,0,0>, cudaFuncAttributeMaxDynamicSharedMemorySize, SM00);
    cudaFuncSetAttribute(gemm_mma<1,1,0,0>, cudaFuncAttributeMaxDynamicSharedMemorySize, SM11);
    cudaFuncSetAttribute(gemm_mma<0,1,2,0>, cudaFuncAttributeMaxDynamicSharedMemorySize, SM01);
    cudaFuncSetAttribute(gemm_mma<0,1,1,1>, cudaFuncAttributeMaxDynamicSharedMemorySize, SM01);
    cudaFuncSetAttribute(gemm_mma<0,1,0,0>, cudaFuncAttributeMaxDynamicSharedMemorySize, SM01);

    // 1. normalize phi
    phi_norm_kernel<<<(DP * DD + 255) / 256, 256>>>(phi, phin);

    // 2. logits[8192,1024] = x @ phin^T   (A row-major, B = phin [N][K])
    gemm_mma<0,0,0,0><<<dim3(DS / 128, (DB * DM) / 128, 1), 256, SM00>>>(
        x, phin, logits, nullptr, DD, DD, DD, DS, 0, 0, 0, 0, 0);

    // 3. softmaxes
    softmax_row_kernel<<<DB * DM, 256>>>(logits, Cbuf);
    softmax_col_kernel<<<dim3(DS / 32, DB), dim3(32, 8)>>>(logits, Dbuf);

    // 4. Xs[b][s][d] = D_b^T @ x_b   (A = D [K=m][M=s], B = x [K=m][N=d])
    gemm_mma<1,1,0,0><<<dim3(DD / 128, DS / 128, DB), 256, SM11>>>(
        Dbuf, x, Xs, nullptr, DM, DS, DD, DD,
        (long long)DM * DS, (long long)DM * DD, (long long)DS * DD, 0, 0);

    // 5. LayerNorm + gather into expert layout
    layernorm_kernel<<<DB * DS, 256>>>(Xs, LN, ln_g, ln_b);

    // 6. hdn[n][128][h] = LN[n] @ w1[n] + b1, GELU   (B = w1 [K=d][N=h])
    gemm_mma<0,1,2,0><<<dim3(DH / 128, 1, DN), 256, SM01>>>(
        LN, w1, hdn, b1, DD, DD, DH, DH,
        (long long)128 * DD, (long long)DD * DH, (long long)128 * DH, DH, 0);

    // 7. Ys[b][n*16+p][d] = hdn[n] @ w2[n] + b2   (B = w2 [K=h][N=d], scattered C)
    gemm_mma<0,1,1,1><<<dim3(DD / 128, 1, DN), 256, SM01>>>(
        hdn, w2, Ys, b2, DH, DH, DD, DD,
        (long long)128 * DH, (long long)DH * DD, (long long)DP * DD, DD,
        (long long)DS * DD);

    // 8. Y[b][m][d] = C_b @ Ys_b   (A row-major, B = Ys [K=s][N=d])
    gemm_mma<0,1,0,0><<<dim3(DD / 128, DM / 128, DB), 256, SM01>>>(
        Cbuf, Ys, out, nullptr, DS, DS, DD, DD,
        (long long)DM * DS, (long long)DS * DD, (long long)DM * DD, 0, 0);
}

// round 4
// speedup vs baseline: 2.7030x; 1.2330x over previous
#include <cuda_runtime.h>
#include <cuda_bf16.h>
#include <math.h>
#include <cstdint>

// ---------------- dimensions ----------------
#define DB 8
#define DM 1024
#define DD 768
#define DN 64
#define DP 16
#define DH 1536
#define DS 1024   // n*p

// ---------------- scratch ----------------
__device__ float g_phin[DN * DP * DD];
__device__ float g_logits[DB * DM * DS];
__device__ float g_D[DB * DM * DS];
__device__ float g_C[DB * DM * DS];
__device__ float g_Xs[DB * DS * DD];
__device__ float g_LN[DN * DB * DP * DD];       // [n][b*16+p][d]
__device__ float g_hdn[DN * (DB * DP) * DH];    // [n][128][h]
__device__ float g_Ys[DB * DS * DD];            // [b][s][d]

// ================= helpers =================
__device__ __forceinline__ uint32_t smem_to_u32(const void* p) {
    uint32_t a;
    asm("{ .reg .u64 t; cvta.to.shared.u64 t, %1; cvt.u32.u64 %0, t; }" : "=r"(a) : "l"(p));
    return a;
}

// fast split: hi = truncate-to-bf16 (bit mask), lo = rn(x - hi)
__device__ __forceinline__ void split4(float4 v, uint32_t& h01, uint32_t& h23,
                                       uint32_t& l01, uint32_t& l23) {
    uint32_t ux = __float_as_uint(v.x), uy = __float_as_uint(v.y);
    uint32_t uz = __float_as_uint(v.z), uw = __float_as_uint(v.w);
    h01 = __byte_perm(ux, uy, 0x7632);
    h23 = __byte_perm(uz, uw, 0x7632);
    float hx = __uint_as_float(ux & 0xFFFF0000u);
    float hy = __uint_as_float(uy & 0xFFFF0000u);
    float hz = __uint_as_float(uz & 0xFFFF0000u);
    float hw = __uint_as_float(uw & 0xFFFF0000u);
    asm("cvt.rn.bf16x2.f32 %0, %1, %2;" : "=r"(l01) : "f"(v.y - hy), "f"(v.x - hx));
    asm("cvt.rn.bf16x2.f32 %0, %1, %2;" : "=r"(l23) : "f"(v.w - hw), "f"(v.z - hz));
}

__device__ __forceinline__ void ldsm_x4(uint32_t* r, uint32_t addr) {
    asm volatile("ldmatrix.sync.aligned.m8n8.x4.shared.b16 {%0,%1,%2,%3}, [%4];"
                 : "=r"(r[0]), "=r"(r[1]), "=r"(r[2]), "=r"(r[3]) : "r"(addr));
}
__device__ __forceinline__ void ldsm_x4_t(uint32_t* r, uint32_t addr) {
    asm volatile("ldmatrix.sync.aligned.m8n8.x4.trans.shared.b16 {%0,%1,%2,%3}, [%4];"
                 : "=r"(r[0]), "=r"(r[1]), "=r"(r[2]), "=r"(r[3]) : "r"(addr));
}
__device__ __forceinline__ void mma_bf16(float* d, const uint32_t* a, const uint32_t* b) {
    asm volatile(
        "mma.sync.aligned.m16n8k16.row.col.f32.bf16.bf16.f32 "
        "{%0,%1,%2,%3}, {%4,%5,%6,%7}, {%8,%9}, {%0,%1,%2,%3};"
        : "+f"(d[0]), "+f"(d[1]), "+f"(d[2]), "+f"(d[3])
        : "r"(a[0]), "r"(a[1]), "r"(a[2]), "r"(a[3]), "r"(b[0]), "r"(b[1]));
}

// ================= elementwise kernels =================
__global__ void phi_norm_kernel(const float* __restrict__ phi, float* __restrict__ phin) {
    int i = blockIdx.x * blockDim.x + threadIdx.x;
    if (i >= DP * DD) return;
    float s = 0.f;
#pragma unroll 4
    for (int n = 0; n < DN; n++) { float v = phi[n * (DP * DD) + i]; s += v * v; }
    float r = rsqrtf(s + 1e-6f);
#pragma unroll 4
    for (int n = 0; n < DN; n++) phin[n * (DP * DD) + i] = phi[n * (DP * DD) + i] * r;
}

__global__ void softmax_row_kernel(const float* __restrict__ L, float* __restrict__ O) {
    const float* Lr = L + (size_t)blockIdx.x * DS;
    float* Or = O + (size_t)blockIdx.x * DS;
    int t = threadIdx.x;
    float v[4]; float mx = -1e30f;
#pragma unroll
    for (int j = 0; j < 4; j++) { v[j] = Lr[t + j * 256]; mx = fmaxf(mx, v[j]); }
    __shared__ float sd[256];
    sd[t] = mx; __syncthreads();
    for (int off = 128; off > 0; off >>= 1) { if (t < off) sd[t] = fmaxf(sd[t], sd[t + off]); __syncthreads(); }
    mx = sd[0]; __syncthreads();
    float sum = 0.f;
#pragma unroll
    for (int j = 0; j < 4; j++) { v[j] = expf(v[j] - mx); sum += v[j]; }
    sd[t] = sum; __syncthreads();
    for (int off = 128; off > 0; off >>= 1) { if (t < off) sd[t] += sd[t + off]; __syncthreads(); }
    float inv = 1.f / sd[0];
#pragma unroll
    for (int j = 0; j < 4; j++) Or[t + j * 256] = v[j] * inv;
}

// 512 threads: (32, 16)
__global__ void softmax_col_kernel(const float* __restrict__ L, float* __restrict__ O) {
    int b = blockIdx.y;
    int s = blockIdx.x * 32 + threadIdx.x;
    int ty = threadIdx.y;   // 0..15
    const float* Lb = L + (size_t)b * DM * DS;
    float* Ob = O + (size_t)b * DM * DS;
    __shared__ float red[16][32];
    float mx = -1e30f;
    for (int m = ty; m < DM; m += 16) mx = fmaxf(mx, Lb[(size_t)m * DS + s]);
    red[ty][threadIdx.x] = mx; __syncthreads();
    if (ty == 0) {
        float v = red[0][threadIdx.x];
#pragma unroll
        for (int i = 1; i < 16; i++) v = fmaxf(v, red[i][threadIdx.x]);
        red[0][threadIdx.x] = v;
    }
    __syncthreads();
    mx = red[0][threadIdx.x]; __syncthreads();
    float sum = 0.f;
    for (int m = ty; m < DM; m += 16) sum += expf(Lb[(size_t)m * DS + s] - mx);
    red[ty][threadIdx.x] = sum; __syncthreads();
    if (ty == 0) {
        float v = 0.f;
#pragma unroll
        for (int i = 0; i < 16; i++) v += red[i][threadIdx.x];
        red[0][threadIdx.x] = v;
    }
    __syncthreads();
    float inv = 1.f / red[0][threadIdx.x];
    for (int m = ty; m < DM; m += 16)
        Ob[(size_t)m * DS + s] = expf(Lb[(size_t)m * DS + s] - mx) * inv;
}

// LayerNorm: read Xs [b][n*16+p][d], write LN [n][b*16+p][d]
__global__ void layernorm_kernel(const float* __restrict__ X, float* __restrict__ Yo,
                                 const float* __restrict__ g, const float* __restrict__ bb) {
    int row = blockIdx.x;
    int b = row >> 10;
    int slot = row & 1023;
    int n = slot >> 4;
    int p = slot & 15;
    const float* Xr = X + (size_t)row * DD;
    float* Yr = Yo + ((size_t)n * 128 + b * 16 + p) * DD;
    __shared__ float sh[DD];
    __shared__ float red[256];
    int t = threadIdx.x;
    float ls = 0.f;
    for (int j = t; j < DD; j += 256) { float v = Xr[j]; sh[j] = v; ls += v; }
    red[t] = ls; __syncthreads();
    for (int off = 128; off > 0; off >>= 1) { if (t < off) red[t] += red[t + off]; __syncthreads(); }
    float mu = red[0] * (1.0f / DD); __syncthreads();
    float lv = 0.f;
    for (int j = t; j < DD; j += 256) { float dv = sh[j] - mu; lv += dv * dv; }
    red[t] = lv; __syncthreads();
    for (int off = 128; off > 0; off >>= 1) { if (t < off) red[t] += red[t + off]; __syncthreads(); }
    float is = rsqrtf(red[0] * (1.0f / DD) + 1e-5f); __syncthreads();
    for (int j = t; j < DD; j += 256)
        Yr[j] = (sh[j] - mu) * is * g[n * DD + j] + bb[n * DD + j];
}

// ================= mma.sync GEMM =================
// CTA tile 128x128, kc=32, 3-term bf16 split, double-buffered, ONE sync/iter.
// TA/TB: 0 = row-major [row][K], 1 = K-major [K][row]
// EPI: 0 none, 1 +bias, 2 +bias+gelu ; CSC: 1 = scattered output rows
template <int TA, int TB, int EPI, int CSC>
__global__ void __launch_bounds__(256)
gemm_mma(const float* __restrict__ A, const float* __restrict__ B,
         float* __restrict__ C, const float* __restrict__ bias,
         int K, int lda, int ldb, int ldc,
         long long aBS, long long bBS, long long cBS, int biasBS, long long c_sb) {
    constexpr int AROW = TA ? 272 : 80;
    constexpr int ASZ1 = TA ? 32 * 272 : 128 * 80;
    constexpr int BROW = TB ? 272 : 80;
    constexpr int BSZ1 = TB ? 32 * 272 : 128 * 80;
    constexpr int STAGE = 2 * ASZ1 + 2 * BSZ1;
    extern __shared__ char smem[];
    const uint32_t sm0 = smem_to_u32(smem);

    const int tid = threadIdx.x;
    const int l = tid & 31;
    const int wid = tid >> 5;
    const int wm = wid & 3;
    const int wn = wid >> 2;
    const int z = blockIdx.z;
    const int bm = blockIdx.y * 128;
    const int bn = blockIdx.x * 128;
    const int NC = K >> 5;

    const float* Ab = A + (size_t)z * aBS + (TA ? (size_t)bm : (size_t)bm * lda);
    const float* Bb = B + (size_t)z * bBS + (TB ? (size_t)bn : (size_t)bn * ldb);

    int a_r, a_c, b_r, b_c;
    if (TA) { a_r = tid >> 3; a_c = (tid & 7) * 16; } else { a_r = tid >> 1; a_c = (tid & 1) * 16; }
    if (TB) { b_r = tid >> 3; b_c = (tid & 7) * 16; } else { b_r = tid >> 1; b_c = (tid & 1) * 16; }

    float4 ra[4], rb[4];

    auto LDG = [&](int c) {
        int k0 = c * 32;
        const float* ap = TA ? (Ab + (size_t)(k0 + a_r) * lda + a_c)
                             : (Ab + (size_t)a_r * lda + k0 + a_c);
        const float* bp = TB ? (Bb + (size_t)(k0 + b_r) * ldb + b_c)
                             : (Bb + (size_t)b_r * ldb + k0 + b_c);
#pragma unroll
        for (int i = 0; i < 4; i++) {
            ra[i] = *(const float4*)(ap + 4 * i);
            rb[i] = *(const float4*)(bp + 4 * i);
        }
    };

    auto STS = [&](int s) {
        char* st = smem + s * STAGE;
        char* ahis = st;
        char* alos = st + ASZ1;
        char* bhis = st + 2 * ASZ1;
        char* blos = st + 2 * ASZ1 + BSZ1;
        int aoff = a_r * AROW + a_c * 2;
        int boff = b_r * BROW + b_c * 2;
#pragma unroll
        for (int i = 0; i < 4; i++) {
            uint32_t h01, h23, l01, l23;
            split4(ra[i], h01, h23, l01, l23);
            *(uint2*)(ahis + aoff + i * 8) = make_uint2(h01, h23);
            *(uint2*)(alos + aoff + i * 8) = make_uint2(l01, l23);
            split4(rb[i], h01, h23, l01, l23);
            *(uint2*)(bhis + boff + i * 8) = make_uint2(h01, h23);
            *(uint2*)(blos + boff + i * 8) = make_uint2(l01, l23);
        }
    };

    float acc[2][8][4];
#pragma unroll
    for (int mt = 0; mt < 2; mt++)
#pragma unroll
        for (int nt = 0; nt < 8; nt++)
#pragma unroll
            for (int q = 0; q < 4; q++) acc[mt][nt][q] = 0.f;

    auto COMPUTE = [&](int s) {
        uint32_t sbA = sm0 + s * STAGE;
        uint32_t sbB = sbA + 2 * ASZ1;
#pragma unroll
        for (int ks = 0; ks < 2; ks++) {
            uint32_t ahi[2][4], alo[2][4];
#pragma unroll
            for (int mt = 0; mt < 2; mt++) {
                int mr = wm * 32 + mt * 16;
                if (TA) {
                    int krow = ks * 16 + (l & 7) + ((l >> 4) << 3);
                    int col = mr + (((l >> 3) & 1) << 3);
                    uint32_t addr = sbA + krow * 272 + col * 2;
                    ldsm_x4_t(ahi[mt], addr);
                    ldsm_x4_t(alo[mt], addr + ASZ1);
                } else {
                    int row = mr + (l & 15);
                    uint32_t addr = sbA + row * 80 + ks * 32 + ((l >> 4) & 1) * 16;
                    ldsm_x4(ahi[mt], addr);
                    ldsm_x4(alo[mt], addr + ASZ1);
                }
            }
#pragma unroll
            for (int np = 0; np < 4; np++) {          // pairs of n-tiles
                int nr = wn * 64 + np * 16;
                uint32_t bhi[4], blo[4];
                if (TB) {
                    int krow = ks * 16 + (l & 7) + (((l >> 3) & 1) << 3);
                    int col = nr + ((l >> 4) << 3);
                    uint32_t addr = sbB + krow * 272 + col * 2;
                    ldsm_x4_t(bhi, addr);
                    ldsm_x4_t(blo, addr + BSZ1);
                } else {
                    int row = nr + (l & 7) + ((l >> 4) << 3);
                    uint32_t addr = sbB + row * 80 + ks * 32 + (((l >> 3) & 1) << 4);
                    ldsm_x4(bhi, addr);
                    ldsm_x4(blo, addr + BSZ1);
                }
#pragma unroll
                for (int half = 0; half < 2; half++) {
                    int nt = np * 2 + half;
#pragma unroll
                    for (int mt = 0; mt < 2; mt++) {
                        mma_bf16(acc[mt][nt], ahi[mt], bhi + 2 * half);
                        mma_bf16(acc[mt][nt], alo[mt], bhi + 2 * half);
                        mma_bf16(acc[mt][nt], ahi[mt], blo + 2 * half);
                    }
                }
            }
        }
    };

    LDG(0);
    STS(0);
    if (NC > 1) LDG(1);
    __syncthreads();
    for (int c = 0; c < NC; c++) {
        if (c + 1 < NC) STS((c + 1) & 1);
        if (c + 2 < NC) LDG(c + 2);
        COMPUTE(c & 1);
        __syncthreads();
    }

    // ---------------- epilogue via smem staging ----------------
    float* Cs = (float*)smem;   // [128][132]
#pragma unroll
    for (int mt = 0; mt < 2; mt++) {
#pragma unroll
        for (int nt = 0; nt < 8; nt++) {
            int r0 = wm * 32 + mt * 16 + (l >> 2);
            int c0 = wn * 64 + nt * 8 + (l & 3) * 2;
            Cs[r0 * 132 + c0] = acc[mt][nt][0];
            Cs[r0 * 132 + c0 + 1] = acc[mt][nt][1];
            Cs[(r0 + 8) * 132 + c0] = acc[mt][nt][2];
            Cs[(r0 + 8) * 132 + c0 + 1] = acc[mt][nt][3];
        }
    }
    __syncthreads();
    const float* bp = (EPI >= 1) ? (bias + (size_t)z * biasBS + bn) : nullptr;
#pragma unroll 4
    for (int i = 0; i < 64; i++) {
        int idx = i * 256 + tid;
        int r = idx >> 7, cc = idx & 127;
        float v = Cs[r * 132 + cc];
        if (EPI >= 1) v += __ldg(bp + cc);
        if (EPI == 2) v = 0.5f * v * (1.0f + erff(v * 0.70710678118654752440f));
        size_t off;
        if (CSC)
            off = (size_t)z * cBS + (size_t)(r >> 4) * c_sb + (size_t)(r & 15) * ldc + bn + cc;
        else
            off = (size_t)z * cBS + (size_t)(bm + r) * ldc + bn + cc;
        C[off] = v;
    }
}

// ================= host launcher =================
extern "C" void kernel_launch(void* const* d_in, const int* in_sizes, int n_in,
                              void* d_out, int out_size) {
    const float* x    = (const float*)d_in[0];
    const float* phi  = (const float*)d_in[1];
    const float* ln_g = (const float*)d_in[2];
    const float* ln_b = (const float*)d_in[3];
    const float* w1   = (const float*)d_in[4];
    const float* b1   = (const float*)d_in[5];
    const float* w2   = (const float*)d_in[6];
    const float* b2   = (const float*)d_in[7];
    float* out = (float*)d_out;

    float *phin, *logits, *Dbuf, *Cbuf, *Xs, *LN, *hdn, *Ys;
    cudaGetSymbolAddress((void**)&phin, g_phin);
    cudaGetSymbolAddress((void**)&logits, g_logits);
    cudaGetSymbolAddress((void**)&Dbuf, g_D);
    cudaGetSymbolAddress((void**)&Cbuf, g_C);
    cudaGetSymbolAddress((void**)&Xs, g_Xs);
    cudaGetSymbolAddress((void**)&LN, g_LN);
    cudaGetSymbolAddress((void**)&hdn, g_hdn);
    cudaGetSymbolAddress((void**)&Ys, g_Ys);

    const int SM00 = 2 * (2 * 128 * 80 + 2 * 128 * 80);       // 81920
    const int SM11 = 2 * (2 * 32 * 272 + 2 * 32 * 272);       // 69632
    const int SM01 = 2 * (2 * 128 * 80 + 2 * 32 * 272);       // 75776
    cudaFuncSetAttribute(gemm_mma<0,0,0,0>, cudaFuncAttributeMaxDynamicSharedMemorySize, SM00);
    cudaFuncSetAttribute(gemm_mma<1,1,0,0>, cudaFuncAttributeMaxDynamicSharedMemorySize, SM11);
    cudaFuncSetAttribute(gemm_mma<0,1,2,0>, cudaFuncAttributeMaxDynamicSharedMemorySize, SM01);
    cudaFuncSetAttribute(gemm_mma<0,1,1,1>, cudaFuncAttributeMaxDynamicSharedMemorySize, SM01);
    cudaFuncSetAttribute(gemm_mma<0,1,0,0>, cudaFuncAttributeMaxDynamicSharedMemorySize, SM01);

    // 1. normalize phi
    phi_norm_kernel<<<(DP * DD + 255) / 256, 256>>>(phi, phin);

    // 2. logits[8192,1024] = x @ phin^T
    gemm_mma<0,0,0,0><<<dim3(DS / 128, (DB * DM) / 128, 1), 256, SM00>>>(
        x, phin, logits, nullptr, DD, DD, DD, DS, 0, 0, 0, 0, 0);

    // 3. softmaxes
    softmax_row_kernel<<<DB * DM, 256>>>(logits, Cbuf);
    softmax_col_kernel<<<dim3(DS / 32, DB), dim3(32, 16)>>>(logits, Dbuf);

    // 4. Xs[b][s][d] = D_b^T @ x_b
    gemm_mma<1,1,0,0><<<dim3(DD / 128, DS / 128, DB), 256, SM11>>>(
        Dbuf, x, Xs, nullptr, DM, DS, DD, DD,
        (long long)DM * DS, (long long)DM * DD, (long long)DS * DD, 0, 0);

    // 5. LayerNorm + gather into expert layout
    layernorm_kernel<<<DB * DS, 256>>>(Xs, LN, ln_g, ln_b);

    // 6. hdn[n][128][h] = LN[n] @ w1[n] + b1, GELU
    gemm_mma<0,1,2,0><<<dim3(DH / 128, 1, DN), 256, SM01>>>(
        LN, w1, hdn, b1, DD, DD, DH, DH,
        (long long)128 * DD, (long long)DD * DH, (long long)128 * DH, DH, 0);

    // 7. Ys[b][n*16+p][d] = hdn[n] @ w2[n] + b2  (scattered C)
    gemm_mma<0,1,1,1><<<dim3(DD / 128, 1, DN), 256, SM01>>>(
        hdn, w2, Ys, b2, DH, DH, DD, DD,
        (long long)128 * DH, (long long)DH * DD, (long long)DP * DD, DD,
        (long long)DS * DD);

    // 8. Y[b][m][d] = C_b @ Ys_b
    gemm_mma<0,1,0,0><<<dim3(DD / 128, DM / 128, DB), 256, SM01>>>(
        Cbuf, Ys, out, nullptr, DS, DS, DD, DD,
        (long long)DM * DS, (long long)DS * DD, (long long)DM * DD, 0, 0);
}

// round 5
// speedup vs baseline: 2.8827x; 1.0665x over previous
#include <cuda_runtime.h>
#include <cuda_bf16.h>
#include <math.h>
#include <cstdint>

// ---------------- dimensions ----------------
#define DB 8
#define DM 1024
#define DD 768
#define DN 64
#define DP 16
#define DH 1536
#define DS 1024   // n*p

// ---------------- scratch ----------------
__device__ float g_phin[DN * DP * DD];
__device__ float g_logits[DB * DM * DS];
__device__ float g_D[DB * DM * DS];
__device__ float g_C[DB * DM * DS];
__device__ float g_Xs[DB * DS * DD];
__device__ float g_LN[DN * DB * DP * DD];       // [n][b*16+p][d]
__device__ float g_hdn[DN * (DB * DP) * DH];    // [n][128][h]
__device__ float g_Ys[DB * DS * DD];            // [b][s][d]

// ================= helpers =================
__device__ __forceinline__ uint32_t smem_to_u32(const void* p) {
    uint32_t a;
    asm("{ .reg .u64 t; cvta.to.shared.u64 t, %1; cvt.u32.u64 %0, t; }" : "=r"(a) : "l"(p));
    return a;
}

// fast split: hi = truncate-to-bf16 (bit mask), lo = rn(x - hi)
__device__ __forceinline__ void split4(float4 v, uint32_t& h01, uint32_t& h23,
                                       uint32_t& l01, uint32_t& l23) {
    uint32_t ux = __float_as_uint(v.x), uy = __float_as_uint(v.y);
    uint32_t uz = __float_as_uint(v.z), uw = __float_as_uint(v.w);
    h01 = __byte_perm(ux, uy, 0x7632);
    h23 = __byte_perm(uz, uw, 0x7632);
    float hx = __uint_as_float(ux & 0xFFFF0000u);
    float hy = __uint_as_float(uy & 0xFFFF0000u);
    float hz = __uint_as_float(uz & 0xFFFF0000u);
    float hw = __uint_as_float(uw & 0xFFFF0000u);
    asm("cvt.rn.bf16x2.f32 %0, %1, %2;" : "=r"(l01) : "f"(v.y - hy), "f"(v.x - hx));
    asm("cvt.rn.bf16x2.f32 %0, %1, %2;" : "=r"(l23) : "f"(v.w - hw), "f"(v.z - hz));
}

__device__ __forceinline__ void ldsm_x4(uint32_t* r, uint32_t addr) {
    asm volatile("ldmatrix.sync.aligned.m8n8.x4.shared.b16 {%0,%1,%2,%3}, [%4];"
                 : "=r"(r[0]), "=r"(r[1]), "=r"(r[2]), "=r"(r[3]) : "r"(addr));
}
__device__ __forceinline__ void ldsm_x4_t(uint32_t* r, uint32_t addr) {
    asm volatile("ldmatrix.sync.aligned.m8n8.x4.trans.shared.b16 {%0,%1,%2,%3}, [%4];"
                 : "=r"(r[0]), "=r"(r[1]), "=r"(r[2]), "=r"(r[3]) : "r"(addr));
}
__device__ __forceinline__ void mma_bf16(float* d, const uint32_t* a, const uint32_t* b) {
    asm volatile(
        "mma.sync.aligned.m16n8k16.row.col.f32.bf16.bf16.f32 "
        "{%0,%1,%2,%3}, {%4,%5,%6,%7}, {%8,%9}, {%0,%1,%2,%3};"
        : "+f"(d[0]), "+f"(d[1]), "+f"(d[2]), "+f"(d[3])
        : "r"(a[0]), "r"(a[1]), "r"(a[2]), "r"(a[3]), "r"(b[0]), "r"(b[1]));
}

// ================= elementwise kernels =================
__global__ void phi_norm_kernel(const float* __restrict__ phi, float* __restrict__ phin) {
    int i = blockIdx.x * blockDim.x + threadIdx.x;
    if (i >= DP * DD) return;
    float s = 0.f;
#pragma unroll 4
    for (int n = 0; n < DN; n++) { float v = phi[n * (DP * DD) + i]; s += v * v; }
    float r = rsqrtf(s + 1e-6f);
#pragma unroll 4
    for (int n = 0; n < DN; n++) phin[n * (DP * DD) + i] = phi[n * (DP * DD) + i] * r;
}

__global__ void softmax_row_kernel(const float* __restrict__ L, float* __restrict__ O) {
    const float* Lr = L + (size_t)blockIdx.x * DS;
    float* Or = O + (size_t)blockIdx.x * DS;
    int t = threadIdx.x;
    float v[4]; float mx = -1e30f;
#pragma unroll
    for (int j = 0; j < 4; j++) { v[j] = Lr[t + j * 256]; mx = fmaxf(mx, v[j]); }
    __shared__ float sd[256];
    sd[t] = mx; __syncthreads();
    for (int off = 128; off > 0; off >>= 1) { if (t < off) sd[t] = fmaxf(sd[t], sd[t + off]); __syncthreads(); }
    mx = sd[0]; __syncthreads();
    float sum = 0.f;
#pragma unroll
    for (int j = 0; j < 4; j++) { v[j] = expf(v[j] - mx); sum += v[j]; }
    sd[t] = sum; __syncthreads();
    for (int off = 128; off > 0; off >>= 1) { if (t < off) sd[t] += sd[t + off]; __syncthreads(); }
    float inv = 1.f / sd[0];
#pragma unroll
    for (int j = 0; j < 4; j++) Or[t + j * 256] = v[j] * inv;
}

// 512 threads: (32, 16)
__global__ void softmax_col_kernel(const float* __restrict__ L, float* __restrict__ O) {
    int b = blockIdx.y;
    int s = blockIdx.x * 32 + threadIdx.x;
    int ty = threadIdx.y;   // 0..15
    const float* Lb = L + (size_t)b * DM * DS;
    float* Ob = O + (size_t)b * DM * DS;
    __shared__ float red[16][32];
    float mx = -1e30f;
    for (int m = ty; m < DM; m += 16) mx = fmaxf(mx, Lb[(size_t)m * DS + s]);
    red[ty][threadIdx.x] = mx; __syncthreads();
    if (ty == 0) {
        float v = red[0][threadIdx.x];
#pragma unroll
        for (int i = 1; i < 16; i++) v = fmaxf(v, red[i][threadIdx.x]);
        red[0][threadIdx.x] = v;
    }
    __syncthreads();
    mx = red[0][threadIdx.x]; __syncthreads();
    float sum = 0.f;
    for (int m = ty; m < DM; m += 16) sum += expf(Lb[(size_t)m * DS + s] - mx);
    red[ty][threadIdx.x] = sum; __syncthreads();
    if (ty == 0) {
        float v = 0.f;
#pragma unroll
        for (int i = 0; i < 16; i++) v += red[i][threadIdx.x];
        red[0][threadIdx.x] = v;
    }
    __syncthreads();
    float inv = 1.f / red[0][threadIdx.x];
    for (int m = ty; m < DM; m += 16)
        Ob[(size_t)m * DS + s] = expf(Lb[(size_t)m * DS + s] - mx) * inv;
}

// LayerNorm: read Xs [b][n*16+p][d], write LN [n][b*16+p][d]
__global__ void layernorm_kernel(const float* __restrict__ X, float* __restrict__ Yo,
                                 const float* __restrict__ g, const float* __restrict__ bb) {
    int row = blockIdx.x;
    int b = row >> 10;
    int slot = row & 1023;
    int n = slot >> 4;
    int p = slot & 15;
    const float* Xr = X + (size_t)row * DD;
    float* Yr = Yo + ((size_t)n * 128 + b * 16 + p) * DD;
    __shared__ float sh[DD];
    __shared__ float red[256];
    int t = threadIdx.x;
    float ls = 0.f;
    for (int j = t; j < DD; j += 256) { float v = Xr[j]; sh[j] = v; ls += v; }
    red[t] = ls; __syncthreads();
    for (int off = 128; off > 0; off >>= 1) { if (t < off) red[t] += red[t + off]; __syncthreads(); }
    float mu = red[0] * (1.0f / DD); __syncthreads();
    float lv = 0.f;
    for (int j = t; j < DD; j += 256) { float dv = sh[j] - mu; lv += dv * dv; }
    red[t] = lv; __syncthreads();
    for (int off = 128; off > 0; off >>= 1) { if (t < off) red[t] += red[t + off]; __syncthreads(); }
    float is = rsqrtf(red[0] * (1.0f / DD) + 1e-5f); __syncthreads();
    for (int j = t; j < DD; j += 256)
        Yr[j] = (sh[j] - mu) * is * g[n * DD + j] + bb[n * DD + j];
}

// ================= mma.sync GEMM =================
// 512 threads, 16 warps in 4x4 grid; warp tile 32x32; CTA tile 128x128, kc=32.
// 3-term bf16 split, double-buffered, ONE sync/iter.
// TA/TB: 0 = row-major [row][K], 1 = K-major [K][row]
// EPI: 0 none, 1 +bias, 2 +bias+gelu ; CSC: 1 = scattered output rows
template <int TA, int TB, int EPI, int CSC>
__global__ void __launch_bounds__(512)
gemm_mma(const float* __restrict__ A, const float* __restrict__ B,
         float* __restrict__ C, const float* __restrict__ bias,
         int K, int lda, int ldb, int ldc,
         long long aBS, long long bBS, long long cBS, int biasBS, long long c_sb) {
    constexpr int ASZ1 = TA ? 32 * 272 : 128 * 80;
    constexpr int BSZ1 = TB ? 32 * 272 : 128 * 80;
    constexpr int STAGE = 2 * ASZ1 + 2 * BSZ1;
    extern __shared__ char smem[];
    const uint32_t sm0 = smem_to_u32(smem);

    const int tid = threadIdx.x;
    const int l = tid & 31;
    const int wid = tid >> 5;       // 0..15
    const int wm = wid & 3;         // 4 M groups of 32 rows
    const int wn = wid >> 2;        // 4 N groups of 32 cols
    const int z = blockIdx.z;
    const int bm = blockIdx.y * 128;
    const int bn = blockIdx.x * 128;
    const int NC = K >> 5;

    const float* Ab = A + (size_t)z * aBS + (TA ? (size_t)bm : (size_t)bm * lda);
    const float* Bb = B + (size_t)z * bBS + (TB ? (size_t)bn : (size_t)bn * ldb);

    float4 ra[2], rb[2];

    auto LDG = [&](int c) {
        int k0 = c * 32;
#pragma unroll
        for (int i = 0; i < 2; i++) {
            int p = tid + i * 512;
            if (TA) ra[i] = *(const float4*)(Ab + (size_t)(k0 + (p >> 5)) * lda + (p & 31) * 4);
            else    ra[i] = *(const float4*)(Ab + (size_t)(p >> 3) * lda + k0 + (p & 7) * 4);
            if (TB) rb[i] = *(const float4*)(Bb + (size_t)(k0 + (p >> 5)) * ldb + (p & 31) * 4);
            else    rb[i] = *(const float4*)(Bb + (size_t)(p >> 3) * ldb + k0 + (p & 7) * 4);
        }
    };

    auto STS = [&](int s) {
        char* st = smem + s * STAGE;
        char* ahis = st;
        char* alos = st + ASZ1;
        char* bhis = st + 2 * ASZ1;
        char* blos = st + 2 * ASZ1 + BSZ1;
#pragma unroll
        for (int i = 0; i < 2; i++) {
            int p = tid + i * 512;
            int aoff = TA ? ((p >> 5) * 272 + (p & 31) * 8) : ((p >> 3) * 80 + (p & 7) * 8);
            int boff = TB ? ((p >> 5) * 272 + (p & 31) * 8) : ((p >> 3) * 80 + (p & 7) * 8);
            uint32_t h01, h23, l01, l23;
            split4(ra[i], h01, h23, l01, l23);
            *(uint2*)(ahis + aoff) = make_uint2(h01, h23);
            *(uint2*)(alos + aoff) = make_uint2(l01, l23);
            split4(rb[i], h01, h23, l01, l23);
            *(uint2*)(bhis + boff) = make_uint2(h01, h23);
            *(uint2*)(blos + boff) = make_uint2(l01, l23);
        }
    };

    float acc[2][4][4];
#pragma unroll
    for (int mt = 0; mt < 2; mt++)
#pragma unroll
        for (int nt = 0; nt < 4; nt++)
#pragma unroll
            for (int q = 0; q < 4; q++) acc[mt][nt][q] = 0.f;

    auto COMPUTE = [&](int s) {
        uint32_t sbA = sm0 + s * STAGE;
        uint32_t sbB = sbA + 2 * ASZ1;
#pragma unroll
        for (int ks = 0; ks < 2; ks++) {
            uint32_t ahi[2][4], alo[2][4];
#pragma unroll
            for (int mt = 0; mt < 2; mt++) {
                int mr = wm * 32 + mt * 16;
                if (TA) {
                    int krow = ks * 16 + (l & 7) + ((l >> 4) << 3);
                    int col = mr + (((l >> 3) & 1) << 3);
                    uint32_t addr = sbA + krow * 272 + col * 2;
                    ldsm_x4_t(ahi[mt], addr);
                    ldsm_x4_t(alo[mt], addr + ASZ1);
                } else {
                    int row = mr + (l & 15);
                    uint32_t addr = sbA + row * 80 + ks * 32 + ((l >> 4) & 1) * 16;
                    ldsm_x4(ahi[mt], addr);
                    ldsm_x4(alo[mt], addr + ASZ1);
                }
            }
#pragma unroll
            for (int np = 0; np < 2; np++) {
                int nr = wn * 32 + np * 16;
                uint32_t bhi[4], blo[4];
                if (TB) {
                    int krow = ks * 16 + (l & 7) + (((l >> 3) & 1) << 3);
                    int col = nr + ((l >> 4) << 3);
                    uint32_t addr = sbB + krow * 272 + col * 2;
                    ldsm_x4_t(bhi, addr);
                    ldsm_x4_t(blo, addr + BSZ1);
                } else {
                    int row = nr + (l & 7) + ((l >> 4) << 3);
                    uint32_t addr = sbB + row * 80 + ks * 32 + (((l >> 3) & 1) << 4);
                    ldsm_x4(bhi, addr);
                    ldsm_x4(blo, addr + BSZ1);
                }
#pragma unroll
                for (int half = 0; half < 2; half++) {
                    int nt = np * 2 + half;
#pragma unroll
                    for (int mt = 0; mt < 2; mt++) {
                        mma_bf16(acc[mt][nt], ahi[mt], bhi + 2 * half);
                        mma_bf16(acc[mt][nt], alo[mt], bhi + 2 * half);
                        mma_bf16(acc[mt][nt], ahi[mt], blo + 2 * half);
                    }
                }
            }
        }
    };

    LDG(0);
    STS(0);
    if (NC > 1) LDG(1);
    __syncthreads();
    for (int c = 0; c < NC; c++) {
        if (c + 1 < NC) STS((c + 1) & 1);
        if (c + 2 < NC) LDG(c + 2);
        COMPUTE(c & 1);
        __syncthreads();
    }

    // ---------------- epilogue via smem staging ----------------
    float* Cs = (float*)smem;   // [128][132]
#pragma unroll
    for (int mt = 0; mt < 2; mt++) {
#pragma unroll
        for (int nt = 0; nt < 4; nt++) {
            int r0 = wm * 32 + mt * 16 + (l >> 2);
            int c0 = wn * 32 + nt * 8 + (l & 3) * 2;
            Cs[r0 * 132 + c0] = acc[mt][nt][0];
            Cs[r0 * 132 + c0 + 1] = acc[mt][nt][1];
            Cs[(r0 + 8) * 132 + c0] = acc[mt][nt][2];
            Cs[(r0 + 8) * 132 + c0 + 1] = acc[mt][nt][3];
        }
    }
    __syncthreads();
    const float* bp = (EPI >= 1) ? (bias + (size_t)z * biasBS + bn) : nullptr;
#pragma unroll 4
    for (int i = 0; i < 32; i++) {
        int idx = i * 512 + tid;
        int r = idx >> 7, cc = idx & 127;
        float v = Cs[r * 132 + cc];
        if (EPI >= 1) v += __ldg(bp + cc);
        if (EPI == 2) v = 0.5f * v * (1.0f + erff(v * 0.70710678118654752440f));
        size_t off;
        if (CSC)
            off = (size_t)z * cBS + (size_t)(r >> 4) * c_sb + (size_t)(r & 15) * ldc + bn + cc;
        else
            off = (size_t)z * cBS + (size_t)(bm + r) * ldc + bn + cc;
        C[off] = v;
    }
}

// ================= host launcher =================
extern "C" void kernel_launch(void* const* d_in, const int* in_sizes, int n_in,
                              void* d_out, int out_size) {
    const float* x    = (const float*)d_in[0];
    const float* phi  = (const float*)d_in[1];
    const float* ln_g = (const float*)d_in[2];
    const float* ln_b = (const float*)d_in[3];
    const float* w1   = (const float*)d_in[4];
    const float* b1   = (const float*)d_in[5];
    const float* w2   = (const float*)d_in[6];
    const float* b2   = (const float*)d_in[7];
    float* out = (float*)d_out;

    float *phin, *logits, *Dbuf, *Cbuf, *Xs, *LN, *hdn, *Ys;
    cudaGetSymbolAddress((void**)&phin, g_phin);
    cudaGetSymbolAddress((void**)&logits, g_logits);
    cudaGetSymbolAddress((void**)&Dbuf, g_D);
    cudaGetSymbolAddress((void**)&Cbuf, g_C);
    cudaGetSymbolAddress((void**)&Xs, g_Xs);
    cudaGetSymbolAddress((void**)&LN, g_LN);
    cudaGetSymbolAddress((void**)&hdn, g_hdn);
    cudaGetSymbolAddress((void**)&Ys, g_Ys);

    const int SM00 = 2 * (2 * 128 * 80 + 2 * 128 * 80);       // 81920
    const int SM11 = 2 * (2 * 32 * 272 + 2 * 32 * 272);       // 69632
    const int SM01 = 2 * (2 * 128 * 80 + 2 * 32 * 272);       // 75776
    cudaFuncSetAttribute(gemm_mma<0,0,0,0>, cudaFuncAttributeMaxDynamicSharedMemorySize, SM00);
    cudaFuncSetAttribute(gemm_mma<1,1,0,0>, cudaFuncAttributeMaxDynamicSharedMemorySize, SM11);
    cudaFuncSetAttribute(gemm_mma<0,1,2,0>, cudaFuncAttributeMaxDynamicSharedMemorySize, SM01);
    cudaFuncSetAttribute(gemm_mma<0,1,1,1>, cudaFuncAttributeMaxDynamicSharedMemorySize, SM01);
    cudaFuncSetAttribute(gemm_mma<0,1,0,0>, cudaFuncAttributeMaxDynamicSharedMemorySize, SM01);

    // 1. normalize phi
    phi_norm_kernel<<<(DP * DD + 255) / 256, 256>>>(phi, phin);

    // 2. logits[8192,1024] = x @ phin^T
    gemm_mma<0,0,0,0><<<dim3(DS / 128, (DB * DM) / 128, 1), 512, SM00>>>(
        x, phin, logits, nullptr, DD, DD, DD, DS, 0, 0, 0, 0, 0);

    // 3. softmaxes
    softmax_row_kernel<<<DB * DM, 256>>>(logits, Cbuf);
    softmax_col_kernel<<<dim3(DS / 32, DB), dim3(32, 16)>>>(logits, Dbuf);

    // 4. Xs[b][s][d] = D_b^T @ x_b
    gemm_mma<1,1,0,0><<<dim3(DD / 128, DS / 128, DB), 512, SM11>>>(
        Dbuf, x, Xs, nullptr, DM, DS, DD, DD,
        (long long)DM * DS, (long long)DM * DD, (long long)DS * DD, 0, 0);

    // 5. LayerNorm + gather into expert layout
    layernorm_kernel<<<DB * DS, 256>>>(Xs, LN, ln_g, ln_b);

    // 6. hdn[n][128][h] = LN[n] @ w1[n] + b1, GELU
    gemm_mma<0,1,2,0><<<dim3(DH / 128, 1, DN), 512, SM01>>>(
        LN, w1, hdn, b1, DD, DD, DH, DH,
        (long long)128 * DD, (long long)DD * DH, (long long)128 * DH, DH, 0);

    // 7. Ys[b][n*16+p][d] = hdn[n] @ w2[n] + b2  (scattered C)
    gemm_mma<0,1,1,1><<<dim3(DD / 128, 1, DN), 512, SM01>>>(
        hdn, w2, Ys, b2, DH, DH, DD, DD,
        (long long)128 * DH, (long long)DH * DD, (long long)DP * DD, DD,
        (long long)DS * DD);

    // 8. Y[b][m][d] = C_b @ Ys_b
    gemm_mma<0,1,0,0><<<dim3(DD / 128, DM / 128, DB), 512, SM01>>>(
        Cbuf, Ys, out, nullptr, DS, DS, DD, DD,
        (long long)DM * DS, (long long)DS * DD, (long long)DM * DD, 0, 0);
}